// round 2
// baseline (speedup 1.0000x reference)
#include <cuda_runtime.h>
#include <math.h>

// ---------------- problem constants ----------------
#define BB    4
#define SSEQ  4096
#define HID   2048
#define HH    16
#define PPAGE 256
#define DDIM  128
#define NPG   16
#define MROWS (BB * SSEQ)          // 16384
#define ATTN_SCALE 0.08838834764831845f   // 1/sqrt(128)

// ---------------- scratch (static device globals; no allocation) ----------------
__device__ float g_q[33554432];    // (B,S,HID) fp32 = 128MB
__device__ float g_k[33554432];
__device__ float g_v[33554432];
__device__ float g_ctx[33554432];  // permuted ctx, laid out as (B, S, HID) for O-proj

// =====================================================================
// SGEMM:  C[m,n] = sum_k A[m,k] * W[n,k] + bias[n]
// M = 16384, N = 2048, K = 2048 fixed. 128x128 block tile, K-tile 16,
// 256 threads, 8x8 per-thread microtile, transposed SMEM staging.
// =====================================================================
__global__ __launch_bounds__(256, 2)
void sgemm_nt_bias(const float* __restrict__ A, const float* __restrict__ W,
                   const float* __restrict__ bias, float* __restrict__ C) {
    const int K  = HID;
    const int Nn = HID;

    __shared__ float As[16][132];
    __shared__ float Bs[16][132];

    const int tid = threadIdx.x;
    const int m0  = blockIdx.y * 128;
    const int n0  = blockIdx.x * 128;
    const int tx  = tid & 15;
    const int ty  = tid >> 4;
    const int lrow = tid >> 2;        // 0..63
    const int lc4  = (tid & 3) << 2;  // 0,4,8,12

    float acc[8][8];
#pragma unroll
    for (int i = 0; i < 8; i++)
#pragma unroll
        for (int j = 0; j < 8; j++) acc[i][j] = 0.0f;

    const float* Aptr = A + (size_t)(m0 + lrow) * K + lc4;
    const float* Wptr = W + (size_t)(n0 + lrow) * K + lc4;

    for (int k0 = 0; k0 < K; k0 += 16) {
#pragma unroll
        for (int half = 0; half < 2; half++) {
            const int row = lrow + half * 64;
            float4 va = *(const float4*)(Aptr + (size_t)half * 64 * K + k0);
            As[lc4 + 0][row] = va.x;
            As[lc4 + 1][row] = va.y;
            As[lc4 + 2][row] = va.z;
            As[lc4 + 3][row] = va.w;
            float4 vb = *(const float4*)(Wptr + (size_t)half * 64 * K + k0);
            Bs[lc4 + 0][row] = vb.x;
            Bs[lc4 + 1][row] = vb.y;
            Bs[lc4 + 2][row] = vb.z;
            Bs[lc4 + 3][row] = vb.w;
        }
        __syncthreads();

#pragma unroll
        for (int kk = 0; kk < 16; kk++) {
            float a[8], b[8];
            *(float4*)&a[0] = *(const float4*)&As[kk][ty * 4];
            *(float4*)&a[4] = *(const float4*)&As[kk][64 + ty * 4];
            *(float4*)&b[0] = *(const float4*)&Bs[kk][tx * 4];
            *(float4*)&b[4] = *(const float4*)&Bs[kk][64 + tx * 4];
#pragma unroll
            for (int i = 0; i < 8; i++)
#pragma unroll
                for (int j = 0; j < 8; j++) acc[i][j] += a[i] * b[j];
        }
        __syncthreads();
    }

    float bv[8];
#pragma unroll
    for (int j = 0; j < 4; j++) {
        bv[j]     = bias[n0 + tx * 4 + j];
        bv[4 + j] = bias[n0 + 64 + tx * 4 + j];
    }

#pragma unroll
    for (int i = 0; i < 8; i++) {
        const int mi = (i < 4) ? (ty * 4 + i) : (64 + ty * 4 + (i - 4));
        float* crow = C + (size_t)(m0 + mi) * Nn + n0;
        float4 r0 = make_float4(acc[i][0] + bv[0], acc[i][1] + bv[1],
                                acc[i][2] + bv[2], acc[i][3] + bv[3]);
        *(float4*)(crow + tx * 4) = r0;
        float4 r1 = make_float4(acc[i][4] + bv[4], acc[i][5] + bv[5],
                                acc[i][6] + bv[6], acc[i][7] + bv[7]);
        *(float4*)(crow + 64 + tx * 4) = r1;
    }
}

// =====================================================================
// Paged attention over the reinterpreted ("scrambled") view.
//
// For paged block (x, h'):  b = x>>4, h = x&15
//   M[p', d'] = Y[b, seq = h'*256 + (p'&1)*128 + d', chan = h*128 + (p'>>1)]
// scores = Mq @ Mk^T * SCALE ; softmax over k' ; ctx = probs @ Mv
// ctx[x,h',p',d'] is written at out2[b, s2 = h*256 + p', c2 = h'*128 + d'].
//
// Grid: 4096 blocks = (x in [0,64)) x (h' in [0,16)) x (q-tile in [0,4)).
// 256 threads. Dynamic SMEM 229632 B:
//   Ssm: 64 x 257 fp32 scores      (16448 floats)
//   Qs : 128(d) x 64(q)            ( 8192 floats)
//   Ks : 128(d) x 256(k)           (32768 floats)
//   Vs : 256(k) x 129(d, padded)   aliases Qs+Ks region after scores
// =====================================================================
#define ATTN_SMEM_FLOATS (64 * 257 + 128 * 64 + 128 * 256)
#define ATTN_SMEM_BYTES  (ATTN_SMEM_FLOATS * 4)

__global__ __launch_bounds__(256, 1)
void attn_kernel(const float* __restrict__ Yq, const float* __restrict__ Yk,
                 const float* __restrict__ Yv, float* __restrict__ Ctx) {
    extern __shared__ float sm[];
    float* Ssm = sm;                 // 64 x 257
    float* Qs  = sm + 64 * 257;      // 128 x 64
    float* Ks  = Qs + 128 * 64;      // 128 x 256
    float* Vs  = Qs;                 // 256 x 129 (reuses Q/K region)

    const int bx = blockIdx.x;
    const int qt = bx & 3;
    const int hp = (bx >> 2) & 15;   // h' (actually the page index)
    const int x  = bx >> 6;
    const int b  = x >> 4;
    const int h  = x & 15;           // real head
    const size_t ybase = (size_t)b * (SSEQ * HID) + (size_t)h * DDIM;
    const int tid = threadIdx.x;
    const int q0  = qt * 64;

    // ---- gather K: Ks[d][p] ----
    for (int idx = tid; idx < 256 * 128; idx += 256) {
        const int p = idx & 255, d = idx >> 8;
        const int seq = hp * 256 + ((p & 1) << 7) + d;
        Ks[d * 256 + p] = Yk[ybase + (size_t)seq * HID + (p >> 1)];
    }
    // ---- gather Q tile: Qs[d][qq] ----
    for (int idx = tid; idx < 64 * 128; idx += 256) {
        const int qq = idx & 63, d = idx >> 6;
        const int p = q0 + qq;
        const int seq = hp * 256 + ((p & 1) << 7) + d;
        Qs[d * 64 + qq] = Yq[ybase + (size_t)seq * HID + (p >> 1)];
    }
    __syncthreads();

    // ---- scores: S[64][256] = Q @ K^T * scale ----
    {
        const int tq = tid >> 4;   // q rows tq*4 .. tq*4+3
        const int tk = tid & 15;   // k cols jg*64 + tk*4 + c
        float sc[4][16];
#pragma unroll
        for (int i = 0; i < 4; i++)
#pragma unroll
            for (int j = 0; j < 16; j++) sc[i][j] = 0.0f;

#pragma unroll 2
        for (int d = 0; d < 128; d++) {
            float qv[4];
#pragma unroll
            for (int i = 0; i < 4; i++) qv[i] = Qs[d * 64 + tq * 4 + i];
            float kv[16];
#pragma unroll
            for (int jg = 0; jg < 4; jg++) {
                float4 k4 = *(const float4*)&Ks[d * 256 + jg * 64 + tk * 4];
                kv[jg * 4 + 0] = k4.x; kv[jg * 4 + 1] = k4.y;
                kv[jg * 4 + 2] = k4.z; kv[jg * 4 + 3] = k4.w;
            }
#pragma unroll
            for (int i = 0; i < 4; i++)
#pragma unroll
                for (int j = 0; j < 16; j++) sc[i][j] += qv[i] * kv[j];
        }
#pragma unroll
        for (int i = 0; i < 4; i++)
#pragma unroll
            for (int jg = 0; jg < 4; jg++)
#pragma unroll
                for (int c = 0; c < 4; c++)
                    Ssm[(tq * 4 + i) * 257 + jg * 64 + tk * 4 + c] =
                        sc[i][jg * 4 + c] * ATTN_SCALE;
    }
    __syncthreads();

    // ---- gather V (overwrites Q/K region): Vs[k][d], pitch 129 ----
    for (int idx = tid; idx < 256 * 128; idx += 256) {
        const int p = idx & 255, d = idx >> 8;
        const int seq = hp * 256 + ((p & 1) << 7) + d;
        Vs[p * 129 + d] = Yv[ybase + (size_t)seq * HID + (p >> 1)];
    }

    // ---- softmax (rows of S); each of 8 warps handles 8 rows ----
    {
        const int warp = tid >> 5, lane = tid & 31;
        for (int r = warp * 8; r < warp * 8 + 8; r++) {
            float* row = Ssm + r * 257;
            float v[8];
            float mx = -1e30f;
#pragma unroll
            for (int j = 0; j < 8; j++) {
                v[j] = row[lane + j * 32];
                mx = fmaxf(mx, v[j]);
            }
#pragma unroll
            for (int off = 16; off > 0; off >>= 1)
                mx = fmaxf(mx, __shfl_xor_sync(0xffffffffu, mx, off));
            float s = 0.0f;
#pragma unroll
            for (int j = 0; j < 8; j++) { v[j] = __expf(v[j] - mx); s += v[j]; }
#pragma unroll
            for (int off = 16; off > 0; off >>= 1)
                s += __shfl_xor_sync(0xffffffffu, s, off);
            const float inv = __frcp_rn(s);
#pragma unroll
            for (int j = 0; j < 8; j++) row[lane + j * 32] = v[j] * inv;
        }
    }
    __syncthreads();

    // ---- O = P @ V ; thread covers q rows tq2*4..+3, d cols j*16 + td ----
    {
        const int tq2 = tid >> 4;
        const int td  = tid & 15;
        float o[4][8];
#pragma unroll
        for (int i = 0; i < 4; i++)
#pragma unroll
            for (int j = 0; j < 8; j++) o[i][j] = 0.0f;

#pragma unroll 4
        for (int k = 0; k < 256; k++) {
            float pv[4];
#pragma unroll
            for (int i = 0; i < 4; i++) pv[i] = Ssm[(tq2 * 4 + i) * 257 + k];
#pragma unroll
            for (int j = 0; j < 8; j++) {
                const float vv = Vs[k * 129 + j * 16 + td];
#pragma unroll
                for (int i = 0; i < 4; i++) o[i][j] += pv[i] * vv;
            }
        }

        // write into O-proj input layout: out2[b, s2 = h*256 + p', c2 = hp*128 + d']
#pragma unroll
        for (int i = 0; i < 4; i++) {
            const int q = q0 + tq2 * 4 + i;
            const size_t orow =
                (size_t)b * (SSEQ * HID) + (size_t)(h * 256 + q) * HID + hp * 128;
#pragma unroll
            for (int j = 0; j < 8; j++) Ctx[orow + j * 16 + td] = o[i][j];
        }
    }
}

// =====================================================================
// launcher
// =====================================================================
extern "C" void kernel_launch(void* const* d_in, const int* in_sizes, int n_in,
                              void* d_out, int out_size) {
    const float* hs = (const float*)d_in[0];
    const float* Wq = (const float*)d_in[1];
    const float* bq = (const float*)d_in[2];
    const float* Wk = (const float*)d_in[3];
    const float* bk = (const float*)d_in[4];
    const float* Wv = (const float*)d_in[5];
    const float* bv = (const float*)d_in[6];
    const float* Wo = (const float*)d_in[7];
    const float* bo = (const float*)d_in[8];

    float *gq, *gk, *gv, *gctx;
    cudaGetSymbolAddress((void**)&gq, g_q);
    cudaGetSymbolAddress((void**)&gk, g_k);
    cudaGetSymbolAddress((void**)&gv, g_v);
    cudaGetSymbolAddress((void**)&gctx, g_ctx);

    cudaFuncSetAttribute(attn_kernel,
                         cudaFuncAttributeMaxDynamicSharedMemorySize,
                         ATTN_SMEM_BYTES);

    dim3 blk(256);
    dim3 grd(HID / 128, MROWS / 128);   // (16, 128)

    sgemm_nt_bias<<<grd, blk>>>(hs, Wq, bq, gq);
    sgemm_nt_bias<<<grd, blk>>>(hs, Wk, bk, gk);
    sgemm_nt_bias<<<grd, blk>>>(hs, Wv, bv, gv);
    attn_kernel<<<4096, blk, ATTN_SMEM_BYTES>>>(gq, gk, gv, gctx);
    sgemm_nt_bias<<<grd, blk>>>(gctx, Wo, bo, (float*)d_out);
}

// round 4
// speedup vs baseline: 1.5689x; 1.5689x over previous
#include <cuda_runtime.h>
#include <cuda_bf16.h>
#include <cstdint>

// ---------------- problem constants ----------------
#define BB    4
#define SSEQ  4096
#define HID   2048
#define HH    16
#define PPAGE 256
#define DDIM  128
#define NPG   16
#define MROWS (BB * SSEQ)          // 16384
#define ATTN_SCALE 0.08838834764831845f   // 1/sqrt(128)

// ---------------- scratch (static device globals; no allocation) ----------------
__device__ float g_q[33554432];    // (B,S,HID) fp32
__device__ float g_k[33554432];
__device__ float g_v[33554432];
__device__ float g_ctx[33554432];  // permuted ctx, (B,S,HID) layout for O-proj
__device__ __nv_bfloat16 g_ah[33554432];   // activation hi split
__device__ __nv_bfloat16 g_al[33554432];   // activation lo split
__device__ __nv_bfloat16 g_wh[4194304];    // weight hi split (reused per GEMM)
__device__ __nv_bfloat16 g_wl[4194304];    // weight lo split

// =====================================================================
// helpers
// =====================================================================
__device__ __forceinline__ uint32_t smem_u32(const void* p) {
    uint32_t a;
    asm("{ .reg .u64 t; cvta.to.shared.u64 t, %1; cvt.u32.u64 %0, t; }"
        : "=r"(a) : "l"(p));
    return a;
}

__device__ __forceinline__ void ldsm_x4(uint32_t& r0, uint32_t& r1,
                                        uint32_t& r2, uint32_t& r3, uint32_t a) {
    asm volatile("ldmatrix.sync.aligned.m8n8.x4.shared.b16 {%0,%1,%2,%3}, [%4];"
                 : "=r"(r0), "=r"(r1), "=r"(r2), "=r"(r3) : "r"(a));
}

__device__ __forceinline__ void mma_bf16(float* c, const uint32_t* a,
                                         const uint32_t* b) {
    asm volatile(
        "mma.sync.aligned.m16n8k16.row.col.f32.bf16.bf16.f32 "
        "{%0,%1,%2,%3}, {%4,%5,%6,%7}, {%8,%9}, {%0,%1,%2,%3};"
        : "+f"(c[0]), "+f"(c[1]), "+f"(c[2]), "+f"(c[3])
        : "r"(a[0]), "r"(a[1]), "r"(a[2]), "r"(a[3]), "r"(b[0]), "r"(b[1]));
}

// =====================================================================
// split: fp32 -> (hi bf16, lo bf16), vectorized x4
// =====================================================================
__global__ void split_bf16(const float4* __restrict__ X,
                           ushort4* __restrict__ H, ushort4* __restrict__ L) {
    const int i = blockIdx.x * 256 + threadIdx.x;
    float4 v = X[i];
    ushort4 h, l;
    {
        __nv_bfloat16 hb = __float2bfloat16(v.x);
        __nv_bfloat16 lb = __float2bfloat16(v.x - __bfloat162float(hb));
        h.x = *reinterpret_cast<unsigned short*>(&hb);
        l.x = *reinterpret_cast<unsigned short*>(&lb);
    }
    {
        __nv_bfloat16 hb = __float2bfloat16(v.y);
        __nv_bfloat16 lb = __float2bfloat16(v.y - __bfloat162float(hb));
        h.y = *reinterpret_cast<unsigned short*>(&hb);
        l.y = *reinterpret_cast<unsigned short*>(&lb);
    }
    {
        __nv_bfloat16 hb = __float2bfloat16(v.z);
        __nv_bfloat16 lb = __float2bfloat16(v.z - __bfloat162float(hb));
        h.z = *reinterpret_cast<unsigned short*>(&hb);
        l.z = *reinterpret_cast<unsigned short*>(&lb);
    }
    {
        __nv_bfloat16 hb = __float2bfloat16(v.w);
        __nv_bfloat16 lb = __float2bfloat16(v.w - __bfloat162float(hb));
        h.w = *reinterpret_cast<unsigned short*>(&hb);
        l.w = *reinterpret_cast<unsigned short*>(&lb);
    }
    H[i] = h;
    L[i] = l;
}

// =====================================================================
// mma.sync GEMM: C[m,n] = sum_k A[m,k]*W[n,k] + bias[n]
// bf16x3: C = Ah@Bh^T + Ah@Bl^T + Al@Bh^T, fp32 accum in registers.
// M=16384, N=2048, K=2048. CTA tile 128x128, BK=32, 256 thr (8 warps 2x4),
// warp tile 64x32, m16n8k16. SMEM double-buffered, 80B row pitch.
// =====================================================================
#define GK 2048
#define GN 2048
#define BKT 32
#define KTILES (GK / BKT)          // 64
#define RPITCH 40                  // bf16 per smem row (32 + 8 pad) = 80B
#define TILE_H (128 * RPITCH)      // halves per tile
#define STAGE_H (4 * TILE_H)       // Ah, Al, Bh, Bl
#define GEMM_SMEM (2 * STAGE_H * 2)  // bytes = 81920

__global__ void __launch_bounds__(256, 1)
gemm_mma_bf16x3(const __nv_bfloat16* __restrict__ Ah,
                const __nv_bfloat16* __restrict__ Al,
                const __nv_bfloat16* __restrict__ Bh,
                const __nv_bfloat16* __restrict__ Bl,
                const float* __restrict__ bias, float* __restrict__ C) {
    extern __shared__ __nv_bfloat16 sm[];
    const uint32_t sb = smem_u32(sm);

    const int tid  = threadIdx.x;
    const int wid  = tid >> 5;
    const int lane = tid & 31;
    const int wm   = wid >> 2;          // 0..1  (M)
    const int wn   = wid & 3;           // 0..3  (N)
    const int n0   = blockIdx.x * 128;
    const int m0   = blockIdx.y * 128;

    // loader mapping: element e in [0,512): row = e>>2, col8 = (e&3)*8
    const int lrow = tid >> 2;          // e = tid   -> rows 0..63
    const int lc   = (tid & 3) * 8;     // bf16 col

    const __nv_bfloat16* gp[4];
    gp[0] = Ah + (size_t)(m0 + lrow) * GK + lc;
    gp[1] = Al + (size_t)(m0 + lrow) * GK + lc;
    gp[2] = Bh + (size_t)(n0 + lrow) * GK + lc;
    gp[3] = Bl + (size_t)(n0 + lrow) * GK + lc;

    // smem byte offset for this thread's store slot (two rows: lrow, lrow+64)
    const uint32_t s0 = (uint32_t)(lrow * RPITCH + lc) * 2;
    const uint32_t s1 = (uint32_t)((lrow + 64) * RPITCH + lc) * 2;

    float acc[4][4][4];
#pragma unroll
    for (int i = 0; i < 4; i++)
#pragma unroll
        for (int j = 0; j < 4; j++)
#pragma unroll
            for (int q = 0; q < 4; q++) acc[i][j][q] = 0.0f;

    // ldmatrix base addresses (lane-dependent part precomputed)
    // A: rows (wm*64 + mf*16 + (lane&15)), byte col = ks*32 + (lane>>4)*16
    // B: rows (wn*32 + nf2*16 + (lane&15)), same col pattern
    const uint32_t lrow16 = (uint32_t)(lane & 15) * (RPITCH * 2);
    const uint32_t lcol16 = (uint32_t)(lane >> 4) * 16;

    // prologue: load stage 0
    uint4 pre[8];
#pragma unroll
    for (int t = 0; t < 4; t++) {
        pre[t * 2 + 0] = *(const uint4*)(gp[t]);
        pre[t * 2 + 1] = *(const uint4*)(gp[t] + (size_t)64 * GK);
    }
#pragma unroll
    for (int t = 0; t < 4; t++) {
        *(uint4*)((char*)sm + t * (TILE_H * 2) + s0) = pre[t * 2 + 0];
        *(uint4*)((char*)sm + t * (TILE_H * 2) + s1) = pre[t * 2 + 1];
    }
    __syncthreads();

    for (int kt = 0; kt < KTILES; kt++) {
        const int buf = kt & 1;
        const uint32_t stage = sb + buf * (STAGE_H * 2);

        // prefetch next k-tile into registers
        if (kt + 1 < KTILES) {
            const int koff = (kt + 1) * BKT;
#pragma unroll
            for (int t = 0; t < 4; t++) {
                pre[t * 2 + 0] = *(const uint4*)(gp[t] + koff);
                pre[t * 2 + 1] = *(const uint4*)(gp[t] + koff + (size_t)64 * GK);
            }
        }

        // compute on current stage: 2 k-steps of 16
#pragma unroll
        for (int ks = 0; ks < 2; ks++) {
            const uint32_t cb = (uint32_t)ks * 32 + lcol16;

            uint32_t ah[4][4], al[4][4];
#pragma unroll
            for (int mf = 0; mf < 4; mf++) {
                const uint32_t roff = (uint32_t)(wm * 64 + mf * 16) * (RPITCH * 2)
                                      + lrow16 + cb;
                ldsm_x4(ah[mf][0], ah[mf][1], ah[mf][2], ah[mf][3],
                        stage + 0 * (TILE_H * 2) + roff);
                ldsm_x4(al[mf][0], al[mf][1], al[mf][2], al[mf][3],
                        stage + 1 * (TILE_H * 2) + roff);
            }
            uint32_t bh[4][2], bl[4][2];
#pragma unroll
            for (int np = 0; np < 2; np++) {   // pairs of n-frags
                const uint32_t roff = (uint32_t)(wn * 32 + np * 16) * (RPITCH * 2)
                                      + lrow16 + cb;
                uint32_t r0, r1, r2, r3;
                ldsm_x4(r0, r1, r2, r3, stage + 2 * (TILE_H * 2) + roff);
                bh[np * 2 + 0][0] = r0; bh[np * 2 + 0][1] = r2;
                bh[np * 2 + 1][0] = r1; bh[np * 2 + 1][1] = r3;
                ldsm_x4(r0, r1, r2, r3, stage + 3 * (TILE_H * 2) + roff);
                bl[np * 2 + 0][0] = r0; bl[np * 2 + 0][1] = r2;
                bl[np * 2 + 1][0] = r1; bl[np * 2 + 1][1] = r3;
            }
#pragma unroll
            for (int mf = 0; mf < 4; mf++)
#pragma unroll
                for (int nf = 0; nf < 4; nf++) {
                    mma_bf16(acc[mf][nf], ah[mf], bh[nf]);
                    mma_bf16(acc[mf][nf], ah[mf], bl[nf]);
                    mma_bf16(acc[mf][nf], al[mf], bh[nf]);
                }
        }

        // store prefetched tile into other buffer
        if (kt + 1 < KTILES) {
            char* dst = (char*)sm + (buf ^ 1) * (STAGE_H * 2);
            __syncthreads();   // everyone done reading buf^1 from 2 iters ago
#pragma unroll
            for (int t = 0; t < 4; t++) {
                *(uint4*)(dst + t * (TILE_H * 2) + s0) = pre[t * 2 + 0];
                *(uint4*)(dst + t * (TILE_H * 2) + s1) = pre[t * 2 + 1];
            }
            __syncthreads();
        }
    }

    // epilogue: acc frag layout m16n8: lane -> (row = l>>2 [+8], col = (l&3)*2)
    const int rbase = m0 + wm * 64 + (lane >> 2);
    const int cbase = n0 + wn * 32 + (lane & 3) * 2;
#pragma unroll
    for (int mf = 0; mf < 4; mf++) {
#pragma unroll
        for (int nf = 0; nf < 4; nf++) {
            const int col = cbase + nf * 8;
            const float b0 = bias[col], b1 = bias[col + 1];
            const int r0 = rbase + mf * 16;
            float* p0 = C + (size_t)r0 * GN + col;
            float* p1 = C + (size_t)(r0 + 8) * GN + col;
            *(float2*)p0 = make_float2(acc[mf][nf][0] + b0, acc[mf][nf][1] + b1);
            *(float2*)p1 = make_float2(acc[mf][nf][2] + b0, acc[mf][nf][3] + b1);
        }
    }
}

// =====================================================================
// Paged attention (unchanged from R1; fp32 FFMA, verified correct).
// M[p',d'] = Y[b, seq = hp*256 + (p'&1)*128 + d', chan = h*128 + (p'>>1)]
// ctx written at out2[b, s2 = h*256 + p', c2 = hp*128 + d'].
// =====================================================================
#define ATTN_SMEM_FLOATS (64 * 257 + 128 * 64 + 128 * 256)
#define ATTN_SMEM_BYTES  (ATTN_SMEM_FLOATS * 4)

__global__ __launch_bounds__(256, 1)
void attn_kernel(const float* __restrict__ Yq, const float* __restrict__ Yk,
                 const float* __restrict__ Yv, float* __restrict__ Ctx) {
    extern __shared__ float sma[];
    float* Ssm = sma;                // 64 x 257
    float* Qs  = sma + 64 * 257;     // 128 x 64
    float* Ks  = Qs + 128 * 64;      // 128 x 256
    float* Vs  = Qs;                 // 256 x 129 (aliases Q/K region)

    const int bx = blockIdx.x;
    const int qt = bx & 3;
    const int hp = (bx >> 2) & 15;
    const int x  = bx >> 6;
    const int b  = x >> 4;
    const int h  = x & 15;
    const size_t ybase = (size_t)b * (SSEQ * HID) + (size_t)h * DDIM;
    const int tid = threadIdx.x;
    const int q0  = qt * 64;

    for (int idx = tid; idx < 256 * 128; idx += 256) {
        const int p = idx & 255, d = idx >> 8;
        const int seq = hp * 256 + ((p & 1) << 7) + d;
        Ks[d * 256 + p] = Yk[ybase + (size_t)seq * HID + (p >> 1)];
    }
    for (int idx = tid; idx < 64 * 128; idx += 256) {
        const int qq = idx & 63, d = idx >> 6;
        const int p = q0 + qq;
        const int seq = hp * 256 + ((p & 1) << 7) + d;
        Qs[d * 64 + qq] = Yq[ybase + (size_t)seq * HID + (p >> 1)];
    }
    __syncthreads();

    {
        const int tq = tid >> 4;
        const int tk = tid & 15;
        float sc[4][16];
#pragma unroll
        for (int i = 0; i < 4; i++)
#pragma unroll
            for (int j = 0; j < 16; j++) sc[i][j] = 0.0f;

#pragma unroll 2
        for (int d = 0; d < 128; d++) {
            float qv[4];
#pragma unroll
            for (int i = 0; i < 4; i++) qv[i] = Qs[d * 64 + tq * 4 + i];
            float kv[16];
#pragma unroll
            for (int jg = 0; jg < 4; jg++) {
                float4 k4 = *(const float4*)&Ks[d * 256 + jg * 64 + tk * 4];
                kv[jg * 4 + 0] = k4.x; kv[jg * 4 + 1] = k4.y;
                kv[jg * 4 + 2] = k4.z; kv[jg * 4 + 3] = k4.w;
            }
#pragma unroll
            for (int i = 0; i < 4; i++)
#pragma unroll
                for (int j = 0; j < 16; j++) sc[i][j] += qv[i] * kv[j];
        }
#pragma unroll
        for (int i = 0; i < 4; i++)
#pragma unroll
            for (int jg = 0; jg < 4; jg++)
#pragma unroll
                for (int cc = 0; cc < 4; cc++)
                    Ssm[(tq * 4 + i) * 257 + jg * 64 + tk * 4 + cc] =
                        sc[i][jg * 4 + cc] * ATTN_SCALE;
    }
    __syncthreads();

    for (int idx = tid; idx < 256 * 128; idx += 256) {
        const int p = idx & 255, d = idx >> 8;
        const int seq = hp * 256 + ((p & 1) << 7) + d;
        Vs[p * 129 + d] = Yv[ybase + (size_t)seq * HID + (p >> 1)];
    }

    {
        const int warp = tid >> 5, lane = tid & 31;
        for (int rr = warp * 8; rr < warp * 8 + 8; rr++) {
            float* row = Ssm + rr * 257;
            float v[8];
            float mx = -1e30f;
#pragma unroll
            for (int j = 0; j < 8; j++) {
                v[j] = row[lane + j * 32];
                mx = fmaxf(mx, v[j]);
            }
#pragma unroll
            for (int off = 16; off > 0; off >>= 1)
                mx = fmaxf(mx, __shfl_xor_sync(0xffffffffu, mx, off));
            float s = 0.0f;
#pragma unroll
            for (int j = 0; j < 8; j++) { v[j] = __expf(v[j] - mx); s += v[j]; }
#pragma unroll
            for (int off = 16; off > 0; off >>= 1)
                s += __shfl_xor_sync(0xffffffffu, s, off);
            const float inv = __frcp_rn(s);
#pragma unroll
            for (int j = 0; j < 8; j++) row[lane + j * 32] = v[j] * inv;
        }
    }
    __syncthreads();

    {
        const int tq2 = tid >> 4;
        const int td  = tid & 15;
        float o[4][8];
#pragma unroll
        for (int i = 0; i < 4; i++)
#pragma unroll
            for (int j = 0; j < 8; j++) o[i][j] = 0.0f;

#pragma unroll 4
        for (int k = 0; k < 256; k++) {
            float pv[4];
#pragma unroll
            for (int i = 0; i < 4; i++) pv[i] = Ssm[(tq2 * 4 + i) * 257 + k];
#pragma unroll
            for (int j = 0; j < 8; j++) {
                const float vv = Vs[k * 129 + j * 16 + td];
#pragma unroll
                for (int i = 0; i < 4; i++) o[i][j] += pv[i] * vv;
            }
        }

#pragma unroll
        for (int i = 0; i < 4; i++) {
            const int q = q0 + tq2 * 4 + i;
            const size_t orow =
                (size_t)b * (SSEQ * HID) + (size_t)(h * 256 + q) * HID + hp * 128;
#pragma unroll
            for (int j = 0; j < 8; j++) Ctx[orow + j * 16 + td] = o[i][j];
        }
    }
}

// =====================================================================
// launcher
// =====================================================================
extern "C" void kernel_launch(void* const* d_in, const int* in_sizes, int n_in,
                              void* d_out, int out_size) {
    const float* hs = (const float*)d_in[0];
    const float* Wq = (const float*)d_in[1];
    const float* bq = (const float*)d_in[2];
    const float* Wk = (const float*)d_in[3];
    const float* bk = (const float*)d_in[4];
    const float* Wv = (const float*)d_in[5];
    const float* bv = (const float*)d_in[6];
    const float* Wo = (const float*)d_in[7];
    const float* bo = (const float*)d_in[8];

    float *gq, *gk, *gv, *gctx;
    __nv_bfloat16 *gah, *gal, *gwh, *gwl;
    cudaGetSymbolAddress((void**)&gq, g_q);
    cudaGetSymbolAddress((void**)&gk, g_k);
    cudaGetSymbolAddress((void**)&gv, g_v);
    cudaGetSymbolAddress((void**)&gctx, g_ctx);
    cudaGetSymbolAddress((void**)&gah, g_ah);
    cudaGetSymbolAddress((void**)&gal, g_al);
    cudaGetSymbolAddress((void**)&gwh, g_wh);
    cudaGetSymbolAddress((void**)&gwl, g_wl);

    cudaFuncSetAttribute(attn_kernel,
                         cudaFuncAttributeMaxDynamicSharedMemorySize, ATTN_SMEM_BYTES);
    cudaFuncSetAttribute(gemm_mma_bf16x3,
                         cudaFuncAttributeMaxDynamicSharedMemorySize, GEMM_SMEM);

    const dim3 blk(256);
    const dim3 ggrd(GN / 128, MROWS / 128);     // (16, 128)
    const int ACT4 = MROWS * HID / 4;           // 8388608
    const int W4   = HID * HID / 4;             // 1048576

    split_bf16<<<ACT4 / 256, blk>>>((const float4*)hs, (ushort4*)gah, (ushort4*)gal);

    split_bf16<<<W4 / 256, blk>>>((const float4*)Wq, (ushort4*)gwh, (ushort4*)gwl);
    gemm_mma_bf16x3<<<ggrd, blk, GEMM_SMEM>>>(gah, gal, gwh, gwl, bq, gq);
    split_bf16<<<W4 / 256, blk>>>((const float4*)Wk, (ushort4*)gwh, (ushort4*)gwl);
    gemm_mma_bf16x3<<<ggrd, blk, GEMM_SMEM>>>(gah, gal, gwh, gwl, bk, gk);
    split_bf16<<<W4 / 256, blk>>>((const float4*)Wv, (ushort4*)gwh, (ushort4*)gwl);
    gemm_mma_bf16x3<<<ggrd, blk, GEMM_SMEM>>>(gah, gal, gwh, gwl, bv, gv);

    attn_kernel<<<4096, blk, ATTN_SMEM_BYTES>>>(gq, gk, gv, gctx);

    split_bf16<<<ACT4 / 256, blk>>>((const float4*)gctx, (ushort4*)gah, (ushort4*)gal);
    split_bf16<<<W4 / 256, blk>>>((const float4*)Wo, (ushort4*)gwh, (ushort4*)gwl);
    gemm_mma_bf16x3<<<ggrd, blk, GEMM_SMEM>>>(gah, gal, gwh, gwl, bo, (float*)d_out);
}

// round 7
// speedup vs baseline: 1.5701x; 1.0008x over previous
#include <cuda_runtime.h>
#include <cuda_bf16.h>
#include <cstdint>

// ---------------- problem constants ----------------
#define BB    4
#define SSEQ  4096
#define HID   2048
#define HH    16
#define PPAGE 256
#define DDIM  128
#define NPG   16
#define MROWS (BB * SSEQ)          // 16384
#define ATTN_SCALE 0.08838834764831845f   // 1/sqrt(128)

// ---------------- scratch (static device globals; no allocation) ----------------
__device__ float g_q[33554432];    // (B,S,HID) fp32
__device__ float g_k[33554432];
__device__ float g_v[33554432];
__device__ float g_ctx[33554432];  // permuted ctx, (B,S,HID) layout for O-proj
__device__ __nv_bfloat16 g_ah[33554432];   // activation hi split
__device__ __nv_bfloat16 g_al[33554432];   // activation lo split
__device__ __nv_bfloat16 g_wh[4194304];    // weight hi split (reused per GEMM)
__device__ __nv_bfloat16 g_wl[4194304];    // weight lo split

// =====================================================================
// helpers
// =====================================================================
__device__ __forceinline__ uint32_t smem_u32(const void* p) {
    uint32_t a;
    asm("{ .reg .u64 t; cvta.to.shared.u64 t, %1; cvt.u32.u64 %0, t; }"
        : "=r"(a) : "l"(p));
    return a;
}

__device__ __forceinline__ void ldsm_x4(uint32_t& r0, uint32_t& r1,
                                        uint32_t& r2, uint32_t& r3, uint32_t a) {
    asm volatile("ldmatrix.sync.aligned.m8n8.x4.shared.b16 {%0,%1,%2,%3}, [%4];"
                 : "=r"(r0), "=r"(r1), "=r"(r2), "=r"(r3) : "r"(a));
}

__device__ __forceinline__ void mma_bf16(float* c, const uint32_t* a,
                                         const uint32_t* b) {
    asm volatile(
        "mma.sync.aligned.m16n8k16.row.col.f32.bf16.bf16.f32 "
        "{%0,%1,%2,%3}, {%4,%5,%6,%7}, {%8,%9}, {%0,%1,%2,%3};"
        : "+f"(c[0]), "+f"(c[1]), "+f"(c[2]), "+f"(c[3])
        : "r"(a[0]), "r"(a[1]), "r"(a[2]), "r"(a[3]), "r"(b[0]), "r"(b[1]));
}

// =====================================================================
// split: fp32 -> (hi bf16, lo bf16), vectorized x4
// =====================================================================
__global__ void split_bf16(const float4* __restrict__ X,
                           ushort4* __restrict__ H, ushort4* __restrict__ L) {
    const int i = blockIdx.x * 256 + threadIdx.x;
    float4 v = X[i];
    ushort4 h, l;
    {
        __nv_bfloat16 hb = __float2bfloat16(v.x);
        __nv_bfloat16 lb = __float2bfloat16(v.x - __bfloat162float(hb));
        h.x = *reinterpret_cast<unsigned short*>(&hb);
        l.x = *reinterpret_cast<unsigned short*>(&lb);
    }
    {
        __nv_bfloat16 hb = __float2bfloat16(v.y);
        __nv_bfloat16 lb = __float2bfloat16(v.y - __bfloat162float(hb));
        h.y = *reinterpret_cast<unsigned short*>(&hb);
        l.y = *reinterpret_cast<unsigned short*>(&lb);
    }
    {
        __nv_bfloat16 hb = __float2bfloat16(v.z);
        __nv_bfloat16 lb = __float2bfloat16(v.z - __bfloat162float(hb));
        h.z = *reinterpret_cast<unsigned short*>(&hb);
        l.z = *reinterpret_cast<unsigned short*>(&lb);
    }
    {
        __nv_bfloat16 hb = __float2bfloat16(v.w);
        __nv_bfloat16 lb = __float2bfloat16(v.w - __bfloat162float(hb));
        h.w = *reinterpret_cast<unsigned short*>(&hb);
        l.w = *reinterpret_cast<unsigned short*>(&lb);
    }
    H[i] = h;
    L[i] = l;
}

// =====================================================================
// mma.sync GEMM: C[m,n] = sum_k A[m,k]*W[n,k] + bias[n]
// bf16x3: C = Ah@Bh^T + Ah@Bl^T + Al@Bh^T, fp32 accum in registers.
// M=16384, N=2048, K=2048. CTA tile 128x128, BK=32, 256 thr (8 warps 2x4),
// warp tile 64x32, m16n8k16. SMEM double-buffered, 80B row pitch.
// =====================================================================
#define GK 2048
#define GN 2048
#define BKT 32
#define KTILES (GK / BKT)          // 64
#define RPITCH 40                  // bf16 per smem row (32 + 8 pad) = 80B
#define TILE_H (128 * RPITCH)      // halves per tile
#define STAGE_H (4 * TILE_H)       // Ah, Al, Bh, Bl
#define GEMM_SMEM (2 * STAGE_H * 2)  // bytes = 81920

__global__ void __launch_bounds__(256, 1)
gemm_mma_bf16x3(const __nv_bfloat16* __restrict__ Ah,
                const __nv_bfloat16* __restrict__ Al,
                const __nv_bfloat16* __restrict__ Bh,
                const __nv_bfloat16* __restrict__ Bl,
                const float* __restrict__ bias, float* __restrict__ C) {
    extern __shared__ __nv_bfloat16 sm[];
    const uint32_t sb = smem_u32(sm);

    const int tid  = threadIdx.x;
    const int wid  = tid >> 5;
    const int lane = tid & 31;
    const int wm   = wid >> 2;          // 0..1  (M)
    const int wn   = wid & 3;           // 0..3  (N)
    const int n0   = blockIdx.x * 128;
    const int m0   = blockIdx.y * 128;

    // loader mapping: element e in [0,512): row = e>>2, col8 = (e&3)*8
    const int lrow = tid >> 2;          // e = tid   -> rows 0..63
    const int lc   = (tid & 3) * 8;     // bf16 col

    const __nv_bfloat16* gp[4];
    gp[0] = Ah + (size_t)(m0 + lrow) * GK + lc;
    gp[1] = Al + (size_t)(m0 + lrow) * GK + lc;
    gp[2] = Bh + (size_t)(n0 + lrow) * GK + lc;
    gp[3] = Bl + (size_t)(n0 + lrow) * GK + lc;

    // smem byte offset for this thread's store slot (two rows: lrow, lrow+64)
    const uint32_t s0 = (uint32_t)(lrow * RPITCH + lc) * 2;
    const uint32_t s1 = (uint32_t)((lrow + 64) * RPITCH + lc) * 2;

    float acc[4][4][4];
#pragma unroll
    for (int i = 0; i < 4; i++)
#pragma unroll
        for (int j = 0; j < 4; j++)
#pragma unroll
            for (int q = 0; q < 4; q++) acc[i][j][q] = 0.0f;

    // ldmatrix base addresses (lane-dependent part precomputed)
    // A: rows (wm*64 + mf*16 + (lane&15)), byte col = ks*32 + (lane>>4)*16
    // B: rows (wn*32 + nf2*16 + (lane&15)), same col pattern
    const uint32_t lrow16 = (uint32_t)(lane & 15) * (RPITCH * 2);
    const uint32_t lcol16 = (uint32_t)(lane >> 4) * 16;

    // prologue: load stage 0
    uint4 pre[8];
#pragma unroll
    for (int t = 0; t < 4; t++) {
        pre[t * 2 + 0] = *(const uint4*)(gp[t]);
        pre[t * 2 + 1] = *(const uint4*)(gp[t] + (size_t)64 * GK);
    }
#pragma unroll
    for (int t = 0; t < 4; t++) {
        *(uint4*)((char*)sm + t * (TILE_H * 2) + s0) = pre[t * 2 + 0];
        *(uint4*)((char*)sm + t * (TILE_H * 2) + s1) = pre[t * 2 + 1];
    }
    __syncthreads();

    for (int kt = 0; kt < KTILES; kt++) {
        const int buf = kt & 1;
        const uint32_t stage = sb + buf * (STAGE_H * 2);

        // prefetch next k-tile into registers
        if (kt + 1 < KTILES) {
            const int koff = (kt + 1) * BKT;
#pragma unroll
            for (int t = 0; t < 4; t++) {
                pre[t * 2 + 0] = *(const uint4*)(gp[t] + koff);
                pre[t * 2 + 1] = *(const uint4*)(gp[t] + koff + (size_t)64 * GK);
            }
        }

        // compute on current stage: 2 k-steps of 16
#pragma unroll
        for (int ks = 0; ks < 2; ks++) {
            const uint32_t cb = (uint32_t)ks * 32 + lcol16;

            uint32_t ah[4][4], al[4][4];
#pragma unroll
            for (int mf = 0; mf < 4; mf++) {
                const uint32_t roff = (uint32_t)(wm * 64 + mf * 16) * (RPITCH * 2)
                                      + lrow16 + cb;
                ldsm_x4(ah[mf][0], ah[mf][1], ah[mf][2], ah[mf][3],
                        stage + 0 * (TILE_H * 2) + roff);
                ldsm_x4(al[mf][0], al[mf][1], al[mf][2], al[mf][3],
                        stage + 1 * (TILE_H * 2) + roff);
            }
            uint32_t bh[4][2], bl[4][2];
#pragma unroll
            for (int np = 0; np < 2; np++) {   // pairs of n-frags
                const uint32_t roff = (uint32_t)(wn * 32 + np * 16) * (RPITCH * 2)
                                      + lrow16 + cb;
                uint32_t r0, r1, r2, r3;
                ldsm_x4(r0, r1, r2, r3, stage + 2 * (TILE_H * 2) + roff);
                bh[np * 2 + 0][0] = r0; bh[np * 2 + 0][1] = r2;
                bh[np * 2 + 1][0] = r1; bh[np * 2 + 1][1] = r3;
                ldsm_x4(r0, r1, r2, r3, stage + 3 * (TILE_H * 2) + roff);
                bl[np * 2 + 0][0] = r0; bl[np * 2 + 0][1] = r2;
                bl[np * 2 + 1][0] = r1; bl[np * 2 + 1][1] = r3;
            }
#pragma unroll
            for (int mf = 0; mf < 4; mf++)
#pragma unroll
                for (int nf = 0; nf < 4; nf++) {
                    mma_bf16(acc[mf][nf], ah[mf], bh[nf]);
                    mma_bf16(acc[mf][nf], ah[mf], bl[nf]);
                    mma_bf16(acc[mf][nf], al[mf], bh[nf]);
                }
        }

        // store prefetched tile into other buffer
        if (kt + 1 < KTILES) {
            char* dst = (char*)sm + (buf ^ 1) * (STAGE_H * 2);
            __syncthreads();   // everyone done reading buf^1 from 2 iters ago
#pragma unroll
            for (int t = 0; t < 4; t++) {
                *(uint4*)(dst + t * (TILE_H * 2) + s0) = pre[t * 2 + 0];
                *(uint4*)(dst + t * (TILE_H * 2) + s1) = pre[t * 2 + 1];
            }
            __syncthreads();
        }
    }

    // epilogue: acc frag layout m16n8: lane -> (row = l>>2 [+8], col = (l&3)*2)
    const int rbase = m0 + wm * 64 + (lane >> 2);
    const int cbase = n0 + wn * 32 + (lane & 3) * 2;
#pragma unroll
    for (int mf = 0; mf < 4; mf++) {
#pragma unroll
        for (int nf = 0; nf < 4; nf++) {
            const int col = cbase + nf * 8;
            const float b0 = bias[col], b1 = bias[col + 1];
            const int r0 = rbase + mf * 16;
            float* p0 = C + (size_t)r0 * GN + col;
            float* p1 = C + (size_t)(r0 + 8) * GN + col;
            *(float2*)p0 = make_float2(acc[mf][nf][0] + b0, acc[mf][nf][1] + b1);
            *(float2*)p1 = make_float2(acc[mf][nf][2] + b0, acc[mf][nf][3] + b1);
        }
    }
}

// =====================================================================
// Paged attention (unchanged from R1; fp32 FFMA, verified correct).
// M[p',d'] = Y[b, seq = hp*256 + (p'&1)*128 + d', chan = h*128 + (p'>>1)]
// ctx written at out2[b, s2 = h*256 + p', c2 = hp*128 + d'].
// =====================================================================
#define ATTN_SMEM_FLOATS (64 * 257 + 128 * 64 + 128 * 256)
#define ATTN_SMEM_BYTES  (ATTN_SMEM_FLOATS * 4)

__global__ __launch_bounds__(256, 1)
void attn_kernel(const float* __restrict__ Yq, const float* __restrict__ Yk,
                 const float* __restrict__ Yv, float* __restrict__ Ctx) {
    extern __shared__ float sma[];
    float* Ssm = sma;                // 64 x 257
    float* Qs  = sma + 64 * 257;     // 128 x 64
    float* Ks  = Qs + 128 * 64;      // 128 x 256
    float* Vs  = Qs;                 // 256 x 129 (aliases Q/K region)

    const int bx = blockIdx.x;
    const int qt = bx & 3;
    const int hp = (bx >> 2) & 15;
    const int x  = bx >> 6;
    const int b  = x >> 4;
    const int h  = x & 15;
    const size_t ybase = (size_t)b * (SSEQ * HID) + (size_t)h * DDIM;
    const int tid = threadIdx.x;
    const int q0  = qt * 64;

    for (int idx = tid; idx < 256 * 128; idx += 256) {
        const int p = idx & 255, d = idx >> 8;
        const int seq = hp * 256 + ((p & 1) << 7) + d;
        Ks[d * 256 + p] = Yk[ybase + (size_t)seq * HID + (p >> 1)];
    }
    for (int idx = tid; idx < 64 * 128; idx += 256) {
        const int qq = idx & 63, d = idx >> 6;
        const int p = q0 + qq;
        const int seq = hp * 256 + ((p & 1) << 7) + d;
        Qs[d * 64 + qq] = Yq[ybase + (size_t)seq * HID + (p >> 1)];
    }
    __syncthreads();

    {
        const int tq = tid >> 4;
        const int tk = tid & 15;
        float sc[4][16];
#pragma unroll
        for (int i = 0; i < 4; i++)
#pragma unroll
            for (int j = 0; j < 16; j++) sc[i][j] = 0.0f;

#pragma unroll 2
        for (int d = 0; d < 128; d++) {
            float qv[4];
#pragma unroll
            for (int i = 0; i < 4; i++) qv[i] = Qs[d * 64 + tq * 4 + i];
            float kv[16];
#pragma unroll
            for (int jg = 0; jg < 4; jg++) {
                float4 k4 = *(const float4*)&Ks[d * 256 + jg * 64 + tk * 4];
                kv[jg * 4 + 0] = k4.x; kv[jg * 4 + 1] = k4.y;
                kv[jg * 4 + 2] = k4.z; kv[jg * 4 + 3] = k4.w;
            }
#pragma unroll
            for (int i = 0; i < 4; i++)
#pragma unroll
                for (int j = 0; j < 16; j++) sc[i][j] += qv[i] * kv[j];
        }
#pragma unroll
        for (int i = 0; i < 4; i++)
#pragma unroll
            for (int jg = 0; jg < 4; jg++)
#pragma unroll
                for (int cc = 0; cc < 4; cc++)
                    Ssm[(tq * 4 + i) * 257 + jg * 64 + tk * 4 + cc] =
                        sc[i][jg * 4 + cc] * ATTN_SCALE;
    }
    __syncthreads();

    for (int idx = tid; idx < 256 * 128; idx += 256) {
        const int p = idx & 255, d = idx >> 8;
        const int seq = hp * 256 + ((p & 1) << 7) + d;
        Vs[p * 129 + d] = Yv[ybase + (size_t)seq * HID + (p >> 1)];
    }

    {
        const int warp = tid >> 5, lane = tid & 31;
        for (int rr = warp * 8; rr < warp * 8 + 8; rr++) {
            float* row = Ssm + rr * 257;
            float v[8];
            float mx = -1e30f;
#pragma unroll
            for (int j = 0; j < 8; j++) {
                v[j] = row[lane + j * 32];
                mx = fmaxf(mx, v[j]);
            }
#pragma unroll
            for (int off = 16; off > 0; off >>= 1)
                mx = fmaxf(mx, __shfl_xor_sync(0xffffffffu, mx, off));
            float s = 0.0f;
#pragma unroll
            for (int j = 0; j < 8; j++) { v[j] = __expf(v[j] - mx); s += v[j]; }
#pragma unroll
            for (int off = 16; off > 0; off >>= 1)
                s += __shfl_xor_sync(0xffffffffu, s, off);
            const float inv = __frcp_rn(s);
#pragma unroll
            for (int j = 0; j < 8; j++) row[lane + j * 32] = v[j] * inv;
        }
    }
    __syncthreads();

    {
        const int tq2 = tid >> 4;
        const int td  = tid & 15;
        float o[4][8];
#pragma unroll
        for (int i = 0; i < 4; i++)
#pragma unroll
            for (int j = 0; j < 8; j++) o[i][j] = 0.0f;

#pragma unroll 4
        for (int k = 0; k < 256; k++) {
            float pv[4];
#pragma unroll
            for (int i = 0; i < 4; i++) pv[i] = Ssm[(tq2 * 4 + i) * 257 + k];
#pragma unroll
            for (int j = 0; j < 8; j++) {
                const float vv = Vs[k * 129 + j * 16 + td];
#pragma unroll
                for (int i = 0; i < 4; i++) o[i][j] += pv[i] * vv;
            }
        }

#pragma unroll
        for (int i = 0; i < 4; i++) {
            const int q = q0 + tq2 * 4 + i;
            const size_t orow =
                (size_t)b * (SSEQ * HID) + (size_t)(h * 256 + q) * HID + hp * 128;
#pragma unroll
            for (int j = 0; j < 8; j++) Ctx[orow + j * 16 + td] = o[i][j];
        }
    }
}

// =====================================================================
// launcher
// =====================================================================
extern "C" void kernel_launch(void* const* d_in, const int* in_sizes, int n_in,
                              void* d_out, int out_size) {
    const float* hs = (const float*)d_in[0];
    const float* Wq = (const float*)d_in[1];
    const float* bq = (const float*)d_in[2];
    const float* Wk = (const float*)d_in[3];
    const float* bk = (const float*)d_in[4];
    const float* Wv = (const float*)d_in[5];
    const float* bv = (const float*)d_in[6];
    const float* Wo = (const float*)d_in[7];
    const float* bo = (const float*)d_in[8];

    float *gq, *gk, *gv, *gctx;
    __nv_bfloat16 *gah, *gal, *gwh, *gwl;
    cudaGetSymbolAddress((void**)&gq, g_q);
    cudaGetSymbolAddress((void**)&gk, g_k);
    cudaGetSymbolAddress((void**)&gv, g_v);
    cudaGetSymbolAddress((void**)&gctx, g_ctx);
    cudaGetSymbolAddress((void**)&gah, g_ah);
    cudaGetSymbolAddress((void**)&gal, g_al);
    cudaGetSymbolAddress((void**)&gwh, g_wh);
    cudaGetSymbolAddress((void**)&gwl, g_wl);

    cudaFuncSetAttribute(attn_kernel,
                         cudaFuncAttributeMaxDynamicSharedMemorySize, ATTN_SMEM_BYTES);
    cudaFuncSetAttribute(gemm_mma_bf16x3,
                         cudaFuncAttributeMaxDynamicSharedMemorySize, GEMM_SMEM);

    const dim3 blk(256);
    const dim3 ggrd(GN / 128, MROWS / 128);     // (16, 128)
    const int ACT4 = MROWS * HID / 4;           // 8388608
    const int W4   = HID * HID / 4;             // 1048576

    split_bf16<<<ACT4 / 256, blk>>>((const float4*)hs, (ushort4*)gah, (ushort4*)gal);

    split_bf16<<<W4 / 256, blk>>>((const float4*)Wq, (ushort4*)gwh, (ushort4*)gwl);
    gemm_mma_bf16x3<<<ggrd, blk, GEMM_SMEM>>>(gah, gal, gwh, gwl, bq, gq);
    split_bf16<<<W4 / 256, blk>>>((const float4*)Wk, (ushort4*)gwh, (ushort4*)gwl);
    gemm_mma_bf16x3<<<ggrd, blk, GEMM_SMEM>>>(gah, gal, gwh, gwl, bk, gk);
    split_bf16<<<W4 / 256, blk>>>((const float4*)Wv, (ushort4*)gwh, (ushort4*)gwl);
    gemm_mma_bf16x3<<<ggrd, blk, GEMM_SMEM>>>(gah, gal, gwh, gwl, bv, gv);

    attn_kernel<<<4096, blk, ATTN_SMEM_BYTES>>>(gq, gk, gv, gctx);

    split_bf16<<<ACT4 / 256, blk>>>((const float4*)gctx, (ushort4*)gah, (ushort4*)gal);
    split_bf16<<<W4 / 256, blk>>>((const float4*)Wo, (ushort4*)gwh, (ushort4*)gwl);
    gemm_mma_bf16x3<<<ggrd, blk, GEMM_SMEM>>>(gah, gal, gwh, gwl, bo, (float*)d_out);
}

// round 12
// speedup vs baseline: 1.5710x; 1.0005x over previous
#include <cuda_runtime.h>
#include <cuda_bf16.h>
#include <cstdint>

// ---------------- problem constants ----------------
#define BB    4
#define SSEQ  4096
#define HID   2048
#define HH    16
#define PPAGE 256
#define DDIM  128
#define NPG   16
#define MROWS (BB * SSEQ)          // 16384
#define ATTN_SCALE 0.08838834764831845f   // 1/sqrt(128)

// ---------------- scratch (static device globals; no allocation) ----------------
__device__ float g_q[33554432];    // (B,S,HID) fp32
__device__ float g_k[33554432];
__device__ float g_v[33554432];
__device__ float g_ctx[33554432];  // permuted ctx, (B,S,HID) layout for O-proj
__device__ __nv_bfloat16 g_ah[33554432];   // activation hi split
__device__ __nv_bfloat16 g_al[33554432];   // activation lo split
__device__ __nv_bfloat16 g_wh[4194304];    // weight hi split (reused per GEMM)
__device__ __nv_bfloat16 g_wl[4194304];    // weight lo split

// =====================================================================
// helpers
// =====================================================================
__device__ __forceinline__ uint32_t smem_u32(const void* p) {
    uint32_t a;
    asm("{ .reg .u64 t; cvta.to.shared.u64 t, %1; cvt.u32.u64 %0, t; }"
        : "=r"(a) : "l"(p));
    return a;
}

__device__ __forceinline__ void ldsm_x4(uint32_t& r0, uint32_t& r1,
                                        uint32_t& r2, uint32_t& r3, uint32_t a) {
    asm volatile("ldmatrix.sync.aligned.m8n8.x4.shared.b16 {%0,%1,%2,%3}, [%4];"
                 : "=r"(r0), "=r"(r1), "=r"(r2), "=r"(r3) : "r"(a));
}

__device__ __forceinline__ void mma_bf16(float* c, const uint32_t* a,
                                         const uint32_t* b) {
    asm volatile(
        "mma.sync.aligned.m16n8k16.row.col.f32.bf16.bf16.f32 "
        "{%0,%1,%2,%3}, {%4,%5,%6,%7}, {%8,%9}, {%0,%1,%2,%3};"
        : "+f"(c[0]), "+f"(c[1]), "+f"(c[2]), "+f"(c[3])
        : "r"(a[0]), "r"(a[1]), "r"(a[2]), "r"(a[3]), "r"(b[0]), "r"(b[1]));
}

// =====================================================================
// split: fp32 -> (hi bf16, lo bf16), vectorized x4
// =====================================================================
__global__ void split_bf16(const float4* __restrict__ X,
                           ushort4* __restrict__ H, ushort4* __restrict__ L) {
    const int i = blockIdx.x * 256 + threadIdx.x;
    float4 v = X[i];
    ushort4 h, l;
    {
        __nv_bfloat16 hb = __float2bfloat16(v.x);
        __nv_bfloat16 lb = __float2bfloat16(v.x - __bfloat162float(hb));
        h.x = *reinterpret_cast<unsigned short*>(&hb);
        l.x = *reinterpret_cast<unsigned short*>(&lb);
    }
    {
        __nv_bfloat16 hb = __float2bfloat16(v.y);
        __nv_bfloat16 lb = __float2bfloat16(v.y - __bfloat162float(hb));
        h.y = *reinterpret_cast<unsigned short*>(&hb);
        l.y = *reinterpret_cast<unsigned short*>(&lb);
    }
    {
        __nv_bfloat16 hb = __float2bfloat16(v.z);
        __nv_bfloat16 lb = __float2bfloat16(v.z - __bfloat162float(hb));
        h.z = *reinterpret_cast<unsigned short*>(&hb);
        l.z = *reinterpret_cast<unsigned short*>(&lb);
    }
    {
        __nv_bfloat16 hb = __float2bfloat16(v.w);
        __nv_bfloat16 lb = __float2bfloat16(v.w - __bfloat162float(hb));
        h.w = *reinterpret_cast<unsigned short*>(&hb);
        l.w = *reinterpret_cast<unsigned short*>(&lb);
    }
    H[i] = h;
    L[i] = l;
}

// =====================================================================
// mma.sync GEMM: C[m,n] = sum_k A[m,k]*W[n,k] + bias[n]
// bf16x3: C = Ah@Bh^T + Ah@Bl^T + Al@Bh^T, fp32 accum in registers.
// M=16384, N=2048, K=2048. CTA tile 128x128, BK=32, 256 thr (8 warps 2x4),
// warp tile 64x32, m16n8k16. SMEM double-buffered, 80B row pitch.
// =====================================================================
#define GK 2048
#define GN 2048
#define BKT 32
#define KTILES (GK / BKT)          // 64
#define RPITCH 40                  // bf16 per smem row (32 + 8 pad) = 80B
#define TILE_H (128 * RPITCH)      // halves per tile
#define STAGE_H (4 * TILE_H)       // Ah, Al, Bh, Bl
#define GEMM_SMEM (2 * STAGE_H * 2)  // bytes = 81920

__global__ void __launch_bounds__(256, 1)
gemm_mma_bf16x3(const __nv_bfloat16* __restrict__ Ah,
                const __nv_bfloat16* __restrict__ Al,
                const __nv_bfloat16* __restrict__ Bh,
                const __nv_bfloat16* __restrict__ Bl,
                const float* __restrict__ bias, float* __restrict__ C) {
    extern __shared__ __nv_bfloat16 sm[];
    const uint32_t sb = smem_u32(sm);

    const int tid  = threadIdx.x;
    const int wid  = tid >> 5;
    const int lane = tid & 31;
    const int wm   = wid >> 2;          // 0..1  (M)
    const int wn   = wid & 3;           // 0..3  (N)
    const int n0   = blockIdx.x * 128;
    const int m0   = blockIdx.y * 128;

    // loader mapping: element e in [0,512): row = e>>2, col8 = (e&3)*8
    const int lrow = tid >> 2;          // e = tid   -> rows 0..63
    const int lc   = (tid & 3) * 8;     // bf16 col

    const __nv_bfloat16* gp[4];
    gp[0] = Ah + (size_t)(m0 + lrow) * GK + lc;
    gp[1] = Al + (size_t)(m0 + lrow) * GK + lc;
    gp[2] = Bh + (size_t)(n0 + lrow) * GK + lc;
    gp[3] = Bl + (size_t)(n0 + lrow) * GK + lc;

    // smem byte offset for this thread's store slot (two rows: lrow, lrow+64)
    const uint32_t s0 = (uint32_t)(lrow * RPITCH + lc) * 2;
    const uint32_t s1 = (uint32_t)((lrow + 64) * RPITCH + lc) * 2;

    float acc[4][4][4];
#pragma unroll
    for (int i = 0; i < 4; i++)
#pragma unroll
        for (int j = 0; j < 4; j++)
#pragma unroll
            for (int q = 0; q < 4; q++) acc[i][j][q] = 0.0f;

    // ldmatrix base addresses (lane-dependent part precomputed)
    // A: rows (wm*64 + mf*16 + (lane&15)), byte col = ks*32 + (lane>>4)*16
    // B: rows (wn*32 + nf2*16 + (lane&15)), same col pattern
    const uint32_t lrow16 = (uint32_t)(lane & 15) * (RPITCH * 2);
    const uint32_t lcol16 = (uint32_t)(lane >> 4) * 16;

    // prologue: load stage 0
    uint4 pre[8];
#pragma unroll
    for (int t = 0; t < 4; t++) {
        pre[t * 2 + 0] = *(const uint4*)(gp[t]);
        pre[t * 2 + 1] = *(const uint4*)(gp[t] + (size_t)64 * GK);
    }
#pragma unroll
    for (int t = 0; t < 4; t++) {
        *(uint4*)((char*)sm + t * (TILE_H * 2) + s0) = pre[t * 2 + 0];
        *(uint4*)((char*)sm + t * (TILE_H * 2) + s1) = pre[t * 2 + 1];
    }
    __syncthreads();

    for (int kt = 0; kt < KTILES; kt++) {
        const int buf = kt & 1;
        const uint32_t stage = sb + buf * (STAGE_H * 2);

        // prefetch next k-tile into registers
        if (kt + 1 < KTILES) {
            const int koff = (kt + 1) * BKT;
#pragma unroll
            for (int t = 0; t < 4; t++) {
                pre[t * 2 + 0] = *(const uint4*)(gp[t] + koff);
                pre[t * 2 + 1] = *(const uint4*)(gp[t] + koff + (size_t)64 * GK);
            }
        }

        // compute on current stage: 2 k-steps of 16
#pragma unroll
        for (int ks = 0; ks < 2; ks++) {
            const uint32_t cb = (uint32_t)ks * 32 + lcol16;

            uint32_t ah[4][4], al[4][4];
#pragma unroll
            for (int mf = 0; mf < 4; mf++) {
                const uint32_t roff = (uint32_t)(wm * 64 + mf * 16) * (RPITCH * 2)
                                      + lrow16 + cb;
                ldsm_x4(ah[mf][0], ah[mf][1], ah[mf][2], ah[mf][3],
                        stage + 0 * (TILE_H * 2) + roff);
                ldsm_x4(al[mf][0], al[mf][1], al[mf][2], al[mf][3],
                        stage + 1 * (TILE_H * 2) + roff);
            }
            uint32_t bh[4][2], bl[4][2];
#pragma unroll
            for (int np = 0; np < 2; np++) {   // pairs of n-frags
                const uint32_t roff = (uint32_t)(wn * 32 + np * 16) * (RPITCH * 2)
                                      + lrow16 + cb;
                uint32_t r0, r1, r2, r3;
                ldsm_x4(r0, r1, r2, r3, stage + 2 * (TILE_H * 2) + roff);
                bh[np * 2 + 0][0] = r0; bh[np * 2 + 0][1] = r2;
                bh[np * 2 + 1][0] = r1; bh[np * 2 + 1][1] = r3;
                ldsm_x4(r0, r1, r2, r3, stage + 3 * (TILE_H * 2) + roff);
                bl[np * 2 + 0][0] = r0; bl[np * 2 + 0][1] = r2;
                bl[np * 2 + 1][0] = r1; bl[np * 2 + 1][1] = r3;
            }
#pragma unroll
            for (int mf = 0; mf < 4; mf++)
#pragma unroll
                for (int nf = 0; nf < 4; nf++) {
                    mma_bf16(acc[mf][nf], ah[mf], bh[nf]);
                    mma_bf16(acc[mf][nf], ah[mf], bl[nf]);
                    mma_bf16(acc[mf][nf], al[mf], bh[nf]);
                }
        }

        // store prefetched tile into other buffer
        if (kt + 1 < KTILES) {
            char* dst = (char*)sm + (buf ^ 1) * (STAGE_H * 2);
            __syncthreads();   // everyone done reading buf^1 from 2 iters ago
#pragma unroll
            for (int t = 0; t < 4; t++) {
                *(uint4*)(dst + t * (TILE_H * 2) + s0) = pre[t * 2 + 0];
                *(uint4*)(dst + t * (TILE_H * 2) + s1) = pre[t * 2 + 1];
            }
            __syncthreads();
        }
    }

    // epilogue: acc frag layout m16n8: lane -> (row = l>>2 [+8], col = (l&3)*2)
    const int rbase = m0 + wm * 64 + (lane >> 2);
    const int cbase = n0 + wn * 32 + (lane & 3) * 2;
#pragma unroll
    for (int mf = 0; mf < 4; mf++) {
#pragma unroll
        for (int nf = 0; nf < 4; nf++) {
            const int col = cbase + nf * 8;
            const float b0 = bias[col], b1 = bias[col + 1];
            const int r0 = rbase + mf * 16;
            float* p0 = C + (size_t)r0 * GN + col;
            float* p1 = C + (size_t)(r0 + 8) * GN + col;
            *(float2*)p0 = make_float2(acc[mf][nf][0] + b0, acc[mf][nf][1] + b1);
            *(float2*)p1 = make_float2(acc[mf][nf][2] + b0, acc[mf][nf][3] + b1);
        }
    }
}

// =====================================================================
// Paged attention (unchanged from R1; fp32 FFMA, verified correct).
// M[p',d'] = Y[b, seq = hp*256 + (p'&1)*128 + d', chan = h*128 + (p'>>1)]
// ctx written at out2[b, s2 = h*256 + p', c2 = hp*128 + d'].
// =====================================================================
#define ATTN_SMEM_FLOATS (64 * 257 + 128 * 64 + 128 * 256)
#define ATTN_SMEM_BYTES  (ATTN_SMEM_FLOATS * 4)

__global__ __launch_bounds__(256, 1)
void attn_kernel(const float* __restrict__ Yq, const float* __restrict__ Yk,
                 const float* __restrict__ Yv, float* __restrict__ Ctx) {
    extern __shared__ float sma[];
    float* Ssm = sma;                // 64 x 257
    float* Qs  = sma + 64 * 257;     // 128 x 64
    float* Ks  = Qs + 128 * 64;      // 128 x 256
    float* Vs  = Qs;                 // 256 x 129 (aliases Q/K region)

    const int bx = blockIdx.x;
    const int qt = bx & 3;
    const int hp = (bx >> 2) & 15;
    const int x  = bx >> 6;
    const int b  = x >> 4;
    const int h  = x & 15;
    const size_t ybase = (size_t)b * (SSEQ * HID) + (size_t)h * DDIM;
    const int tid = threadIdx.x;
    const int q0  = qt * 64;

    for (int idx = tid; idx < 256 * 128; idx += 256) {
        const int p = idx & 255, d = idx >> 8;
        const int seq = hp * 256 + ((p & 1) << 7) + d;
        Ks[d * 256 + p] = Yk[ybase + (size_t)seq * HID + (p >> 1)];
    }
    for (int idx = tid; idx < 64 * 128; idx += 256) {
        const int qq = idx & 63, d = idx >> 6;
        const int p = q0 + qq;
        const int seq = hp * 256 + ((p & 1) << 7) + d;
        Qs[d * 64 + qq] = Yq[ybase + (size_t)seq * HID + (p >> 1)];
    }
    __syncthreads();

    {
        const int tq = tid >> 4;
        const int tk = tid & 15;
        float sc[4][16];
#pragma unroll
        for (int i = 0; i < 4; i++)
#pragma unroll
            for (int j = 0; j < 16; j++) sc[i][j] = 0.0f;

#pragma unroll 2
        for (int d = 0; d < 128; d++) {
            float qv[4];
#pragma unroll
            for (int i = 0; i < 4; i++) qv[i] = Qs[d * 64 + tq * 4 + i];
            float kv[16];
#pragma unroll
            for (int jg = 0; jg < 4; jg++) {
                float4 k4 = *(const float4*)&Ks[d * 256 + jg * 64 + tk * 4];
                kv[jg * 4 + 0] = k4.x; kv[jg * 4 + 1] = k4.y;
                kv[jg * 4 + 2] = k4.z; kv[jg * 4 + 3] = k4.w;
            }
#pragma unroll
            for (int i = 0; i < 4; i++)
#pragma unroll
                for (int j = 0; j < 16; j++) sc[i][j] += qv[i] * kv[j];
        }
#pragma unroll
        for (int i = 0; i < 4; i++)
#pragma unroll
            for (int jg = 0; jg < 4; jg++)
#pragma unroll
                for (int cc = 0; cc < 4; cc++)
                    Ssm[(tq * 4 + i) * 257 + jg * 64 + tk * 4 + cc] =
                        sc[i][jg * 4 + cc] * ATTN_SCALE;
    }
    __syncthreads();

    for (int idx = tid; idx < 256 * 128; idx += 256) {
        const int p = idx & 255, d = idx >> 8;
        const int seq = hp * 256 + ((p & 1) << 7) + d;
        Vs[p * 129 + d] = Yv[ybase + (size_t)seq * HID + (p >> 1)];
    }

    {
        const int warp = tid >> 5, lane = tid & 31;
        for (int rr = warp * 8; rr < warp * 8 + 8; rr++) {
            float* row = Ssm + rr * 257;
            float v[8];
            float mx = -1e30f;
#pragma unroll
            for (int j = 0; j < 8; j++) {
                v[j] = row[lane + j * 32];
                mx = fmaxf(mx, v[j]);
            }
#pragma unroll
            for (int off = 16; off > 0; off >>= 1)
                mx = fmaxf(mx, __shfl_xor_sync(0xffffffffu, mx, off));
            float s = 0.0f;
#pragma unroll
            for (int j = 0; j < 8; j++) { v[j] = __expf(v[j] - mx); s += v[j]; }
#pragma unroll
            for (int off = 16; off > 0; off >>= 1)
                s += __shfl_xor_sync(0xffffffffu, s, off);
            const float inv = __frcp_rn(s);
#pragma unroll
            for (int j = 0; j < 8; j++) row[lane + j * 32] = v[j] * inv;
        }
    }
    __syncthreads();

    {
        const int tq2 = tid >> 4;
        const int td  = tid & 15;
        float o[4][8];
#pragma unroll
        for (int i = 0; i < 4; i++)
#pragma unroll
            for (int j = 0; j < 8; j++) o[i][j] = 0.0f;

#pragma unroll 4
        for (int k = 0; k < 256; k++) {
            float pv[4];
#pragma unroll
            for (int i = 0; i < 4; i++) pv[i] = Ssm[(tq2 * 4 + i) * 257 + k];
#pragma unroll
            for (int j = 0; j < 8; j++) {
                const float vv = Vs[k * 129 + j * 16 + td];
#pragma unroll
                for (int i = 0; i < 4; i++) o[i][j] += pv[i] * vv;
            }
        }

#pragma unroll
        for (int i = 0; i < 4; i++) {
            const int q = q0 + tq2 * 4 + i;
            const size_t orow =
                (size_t)b * (SSEQ * HID) + (size_t)(h * 256 + q) * HID + hp * 128;
#pragma unroll
            for (int j = 0; j < 8; j++) Ctx[orow + j * 16 + td] = o[i][j];
        }
    }
}

// =====================================================================
// launcher
// =====================================================================
extern "C" void kernel_launch(void* const* d_in, const int* in_sizes, int n_in,
                              void* d_out, int out_size) {
    const float* hs = (const float*)d_in[0];
    const float* Wq = (const float*)d_in[1];
    const float* bq = (const float*)d_in[2];
    const float* Wk = (const float*)d_in[3];
    const float* bk = (const float*)d_in[4];
    const float* Wv = (const float*)d_in[5];
    const float* bv = (const float*)d_in[6];
    const float* Wo = (const float*)d_in[7];
    const float* bo = (const float*)d_in[8];

    float *gq, *gk, *gv, *gctx;
    __nv_bfloat16 *gah, *gal, *gwh, *gwl;
    cudaGetSymbolAddress((void**)&gq, g_q);
    cudaGetSymbolAddress((void**)&gk, g_k);
    cudaGetSymbolAddress((void**)&gv, g_v);
    cudaGetSymbolAddress((void**)&gctx, g_ctx);
    cudaGetSymbolAddress((void**)&gah, g_ah);
    cudaGetSymbolAddress((void**)&gal, g_al);
    cudaGetSymbolAddress((void**)&gwh, g_wh);
    cudaGetSymbolAddress((void**)&gwl, g_wl);

    cudaFuncSetAttribute(attn_kernel,
                         cudaFuncAttributeMaxDynamicSharedMemorySize, ATTN_SMEM_BYTES);
    cudaFuncSetAttribute(gemm_mma_bf16x3,
                         cudaFuncAttributeMaxDynamicSharedMemorySize, GEMM_SMEM);

    const dim3 blk(256);
    const dim3 ggrd(GN / 128, MROWS / 128);     // (16, 128)
    const int ACT4 = MROWS * HID / 4;           // 8388608
    const int W4   = HID * HID / 4;             // 1048576

    split_bf16<<<ACT4 / 256, blk>>>((const float4*)hs, (ushort4*)gah, (ushort4*)gal);

    split_bf16<<<W4 / 256, blk>>>((const float4*)Wq, (ushort4*)gwh, (ushort4*)gwl);
    gemm_mma_bf16x3<<<ggrd, blk, GEMM_SMEM>>>(gah, gal, gwh, gwl, bq, gq);
    split_bf16<<<W4 / 256, blk>>>((const float4*)Wk, (ushort4*)gwh, (ushort4*)gwl);
    gemm_mma_bf16x3<<<ggrd, blk, GEMM_SMEM>>>(gah, gal, gwh, gwl, bk, gk);
    split_bf16<<<W4 / 256, blk>>>((const float4*)Wv, (ushort4*)gwh, (ushort4*)gwl);
    gemm_mma_bf16x3<<<ggrd, blk, GEMM_SMEM>>>(gah, gal, gwh, gwl, bv, gv);

    attn_kernel<<<4096, blk, ATTN_SMEM_BYTES>>>(gq, gk, gv, gctx);

    split_bf16<<<ACT4 / 256, blk>>>((const float4*)gctx, (ushort4*)gah, (ushort4*)gal);
    split_bf16<<<W4 / 256, blk>>>((const float4*)Wo, (ushort4*)gwh, (ushort4*)gwl);
    gemm_mma_bf16x3<<<ggrd, blk, GEMM_SMEM>>>(gah, gal, gwh, gwl, bo, (float*)d_out);
}